// round 1
// baseline (speedup 1.0000x reference)
#include <cuda_runtime.h>
#include <math.h>

#define HID 4096
#define LEN 2048
#define VOC 4096

// ---------------- scratch (device globals, no allocation) ----------------
__device__ __align__(16) float g_e[HID];            // embedded token
__device__ __align__(16) float g_alog[LEN];         // attention logits
__device__ __align__(16) float g_attn[LEN];         // attention weights
__device__ __align__(16) float g_ctx_part[32 * HID];// ctx partial sums (32 L-slices)
__device__ __align__(16) float g_ctx[HID];          // context vector
__device__ __align__(16) float g_x[HID];            // LSTM input
__device__ __align__(16) float g_gates[4 * HID];    // i,f,g,o gates
__device__ __align__(16) float g_h[HID];            // h_new
__device__ __align__(16) float g_logits[VOC];       // output logits

// ---------------- helpers ----------------
__device__ __forceinline__ float wred_sum(float v) {
    #pragma unroll
    for (int o = 16; o; o >>= 1) v += __shfl_xor_sync(0xffffffffu, v, o);
    return v;
}
__device__ __forceinline__ float wred_max(float v) {
    #pragma unroll
    for (int o = 16; o; o >>= 1) v = fmaxf(v, __shfl_xor_sync(0xffffffffu, v, o));
    return v;
}

__device__ __forceinline__ float block_sum(float v) {
    __shared__ float sm[33];
    int lane = threadIdx.x & 31, warp = threadIdx.x >> 5;
    v = wred_sum(v);
    if (lane == 0) sm[warp] = v;
    __syncthreads();
    int nw = (blockDim.x + 31) >> 5;
    float r = (threadIdx.x < nw) ? sm[threadIdx.x] : 0.f;
    if (warp == 0) {
        r = wred_sum(r);
        if (lane == 0) sm[32] = r;
    }
    __syncthreads();
    r = sm[32];
    __syncthreads();
    return r;
}

__device__ __forceinline__ float block_max(float v) {
    __shared__ float sm[33];
    int lane = threadIdx.x & 31, warp = threadIdx.x >> 5;
    v = wred_max(v);
    if (lane == 0) sm[warp] = v;
    __syncthreads();
    int nw = (blockDim.x + 31) >> 5;
    float r = (threadIdx.x < nw) ? sm[threadIdx.x] : -INFINITY;
    if (warp == 0) {
        r = wred_max(r);
        if (lane == 0) sm[32] = r;
    }
    __syncthreads();
    r = sm[32];
    __syncthreads();
    return r;
}

// ---------------- kernels ----------------

// embedding gather: g_e = emb[token]
__global__ void k_gather_e(const float* __restrict__ emb, const int* __restrict__ token) {
    int i = blockIdx.x * blockDim.x + threadIdx.x;
    g_e[i] = emb[(size_t)token[0] * HID + i];
}

// out[row] = ACT( W1[row]·v1 + (C2 ? W2[row]·v2 : 0) + b1[row] + (b2 ? b2[row] : 0) )
// warp-per-row, float4 streaming loads.
template<int C1, int C2, int ACT>
__global__ void k_gemv2(const float* __restrict__ W1, int ld1, const float* __restrict__ v1,
                        const float* __restrict__ W2, int ld2, const float* __restrict__ v2,
                        const float* __restrict__ b1, const float* __restrict__ b2,
                        float* __restrict__ out)
{
    const int lane = threadIdx.x & 31;
    const int row  = blockIdx.x * (blockDim.x >> 5) + (threadIdx.x >> 5);

    const float4* w1 = reinterpret_cast<const float4*>(W1 + (size_t)row * ld1);
    const float4* a1 = reinterpret_cast<const float4*>(v1);
    float acc = 0.f;
    #pragma unroll 4
    for (int k = lane; k < C1 / 4; k += 32) {
        float4 w = __ldg(w1 + k);
        float4 x = __ldg(a1 + k);
        acc = fmaf(w.x, x.x, fmaf(w.y, x.y, fmaf(w.z, x.z, fmaf(w.w, x.w, acc))));
    }
    if constexpr (C2 > 0) {
        const float4* w2 = reinterpret_cast<const float4*>(W2 + (size_t)row * ld2);
        const float4* a2 = reinterpret_cast<const float4*>(v2);
        #pragma unroll 4
        for (int k = lane; k < C2 / 4; k += 32) {
            float4 w = __ldg(w2 + k);
            float4 x = __ldg(a2 + k);
            acc = fmaf(w.x, x.x, fmaf(w.y, x.y, fmaf(w.z, x.z, fmaf(w.w, x.w, acc))));
        }
    }
    acc = wred_sum(acc);
    if (lane == 0) {
        acc += b1[row];
        if (b2) acc += b2[row];
        if (ACT == 1) acc = fmaxf(acc, 0.f);
        out[row] = acc;
    }
}

// softmax over 2048 attention logits; writes g_attn and d_out[12288:14336)
__global__ void k_softmax_attn(float* __restrict__ out_attn) {
    const int t = threadIdx.x;           // 256 threads, 8 elems each
    float v[8];
    float m = -INFINITY;
    #pragma unroll
    for (int i = 0; i < 8; i++) {
        v[i] = g_alog[t + 256 * i];
        m = fmaxf(m, v[i]);
    }
    m = block_max(m);
    float s = 0.f;
    #pragma unroll
    for (int i = 0; i < 8; i++) {
        v[i] = expf(v[i] - m);
        s += v[i];
    }
    s = block_sum(s);
    float inv = 1.f / s;
    #pragma unroll
    for (int i = 0; i < 8; i++) {
        float w = v[i] * inv;
        g_attn[t + 256 * i]   = w;
        out_attn[t + 256 * i] = w;
    }
}

// ctx partial: grid(8, 32), block 128. Each block: 512 cols (128 float4) × 64 rows.
__global__ void k_ctx_partial(const float* __restrict__ enc) {
    const int col4 = blockIdx.x * 128 + threadIdx.x;    // 0..1023
    const int l0   = blockIdx.y * 64;
    const float4* e4 = reinterpret_cast<const float4*>(enc);
    float4 acc = make_float4(0.f, 0.f, 0.f, 0.f);
    #pragma unroll 4
    for (int l = l0; l < l0 + 64; ++l) {
        float w = g_attn[l];
        float4 u = __ldg(e4 + (size_t)l * (HID / 4) + col4);
        acc.x = fmaf(w, u.x, acc.x);
        acc.y = fmaf(w, u.y, acc.y);
        acc.z = fmaf(w, u.z, acc.z);
        acc.w = fmaf(w, u.w, acc.w);
    }
    reinterpret_cast<float4*>(g_ctx_part)[blockIdx.y * (HID / 4) + col4] = acc;
}

// ctx reduce: 1024 threads, sum 32 partials per float4 column
__global__ void k_ctx_reduce() {
    const int col4 = blockIdx.x * blockDim.x + threadIdx.x; // 0..1023
    const float4* p = reinterpret_cast<const float4*>(g_ctx_part);
    float4 acc = make_float4(0.f, 0.f, 0.f, 0.f);
    #pragma unroll
    for (int s = 0; s < 32; s++) {
        float4 u = p[s * (HID / 4) + col4];
        acc.x += u.x; acc.y += u.y; acc.z += u.z; acc.w += u.w;
    }
    reinterpret_cast<float4*>(g_ctx)[col4] = acc;
}

// LSTM pointwise: c_new, h_new; writes d_out[4096:8192)=h_new, d_out[8192:12288)=c_new
__global__ void k_lstm(const float* __restrict__ c_in, float* __restrict__ out) {
    const int j = blockIdx.x * blockDim.x + threadIdx.x;  // 0..4095
    float gi = g_gates[j];
    float gf = g_gates[HID + j];
    float gg = g_gates[2 * HID + j];
    float go = g_gates[3 * HID + j];
    float si = 1.f / (1.f + expf(-gi));
    float sf = 1.f / (1.f + expf(-gf));
    float so = 1.f / (1.f + expf(-go));
    float cn = sf * c_in[j] + si * tanhf(gg);
    float hn = so * tanhf(cn);
    g_h[j] = hn;
    out[HID + j]     = hn;
    out[2 * HID + j] = cn;
}

// log-softmax over 4096 logits -> d_out[0:4096)
__global__ void k_logsoftmax(float* __restrict__ out) {
    const int t = threadIdx.x;           // 1024 threads, 4 elems each
    float v[4];
    float m = -INFINITY;
    #pragma unroll
    for (int i = 0; i < 4; i++) {
        v[i] = g_logits[t + 1024 * i];
        m = fmaxf(m, v[i]);
    }
    m = block_max(m);
    float s = 0.f;
    #pragma unroll
    for (int i = 0; i < 4; i++) s += expf(v[i] - m);
    s = block_sum(s);
    float lse = m + logf(s);
    #pragma unroll
    for (int i = 0; i < 4; i++) out[t + 1024 * i] = v[i] - lse;
}

// ---------------- launch ----------------
extern "C" void kernel_launch(void* const* d_in, const int* in_sizes, int n_in,
                              void* d_out, int out_size)
{
    const int*   token  = (const int*)  d_in[0];
    const float* h      = (const float*)d_in[1];
    const float* c      = (const float*)d_in[2];
    const float* enc    = (const float*)d_in[3];
    const float* emb    = (const float*)d_in[4];
    const float* W_attn = (const float*)d_in[5];
    const float* b_attn = (const float*)d_in[6];
    const float* W_comb = (const float*)d_in[7];
    const float* b_comb = (const float*)d_in[8];
    const float* W_ih   = (const float*)d_in[9];
    const float* W_hh   = (const float*)d_in[10];
    const float* b_ih   = (const float*)d_in[11];
    const float* b_hh   = (const float*)d_in[12];
    const float* W_out  = (const float*)d_in[13];
    const float* b_out  = (const float*)d_in[14];
    float* out = (float*)d_out;

    // device addresses of scratch globals
    float *p_e, *p_alog, *p_x, *p_gates, *p_logits, *p_ctx, *p_h;
    cudaGetSymbolAddress((void**)&p_e,      g_e);
    cudaGetSymbolAddress((void**)&p_alog,   g_alog);
    cudaGetSymbolAddress((void**)&p_x,      g_x);
    cudaGetSymbolAddress((void**)&p_gates,  g_gates);
    cudaGetSymbolAddress((void**)&p_logits, g_logits);
    cudaGetSymbolAddress((void**)&p_ctx,    g_ctx);
    cudaGetSymbolAddress((void**)&p_h,      g_h);

    // 1) embedding gather
    k_gather_e<<<HID / 256, 256>>>(emb, token);

    // 2) attention logits: [e;h] @ W_attn.T + b_attn  (2048 rows x 8192 cols)
    k_gemv2<4096, 4096, 0><<<LEN / 8, 256>>>(
        W_attn,         8192, p_e,
        W_attn + 4096,  8192, h,
        b_attn, nullptr, p_alog);

    // 3) softmax -> g_attn and d_out[12288:]
    k_softmax_attn<<<1, 256>>>(out + 3 * HID);

    // 4) ctx = attn_w @ encoder_outputs (deterministic two-stage)
    k_ctx_partial<<<dim3(8, 32), 128>>>(enc);
    k_ctx_reduce<<<4, 256>>>();

    // 5) x = relu([e;ctx] @ W_comb.T + b_comb)  (4096 rows x 8192 cols)
    k_gemv2<4096, 4096, 1><<<HID / 8, 256>>>(
        W_comb,        8192, p_e,
        W_comb + 4096, 8192, p_ctx,
        b_comb, nullptr, p_x);

    // 6) gates = x @ W_ih.T + b_ih + h @ W_hh.T + b_hh  (16384 rows)
    k_gemv2<4096, 4096, 0><<<(4 * HID) / 8, 256>>>(
        W_ih, 4096, p_x,
        W_hh, 4096, h,
        b_ih, b_hh, p_gates);

    // 7) LSTM pointwise -> h_new, c_new (also written to d_out)
    k_lstm<<<HID / 256, 256>>>(c, out);

    // 8) logits = h_new @ W_out.T + b_out  (4096 rows x 4096 cols)
    k_gemv2<4096, 0, 0><<<VOC / 8, 256>>>(
        W_out, 4096, p_h,
        nullptr, 0, nullptr,
        b_out, nullptr, p_logits);

    // 9) log-softmax -> d_out[0:4096)
    k_logsoftmax<<<1, 1024>>>(out);
}

// round 4
// speedup vs baseline: 1.0476x; 1.0476x over previous
#include <cuda_runtime.h>
#include <math.h>

#define HID 4096
#define LEN 2048
#define VOC 4096
#define CTX_SLICES 128   // 16 encoder rows per slice

// ---------------- scratch (device globals, no allocation) ----------------
__device__ __align__(16) float g_alog[LEN];                   // attention logits
__device__ __align__(16) float g_attn[LEN];                   // attention weights
__device__ __align__(16) float g_ctx_part[CTX_SLICES * HID];  // ctx partials (2 MB)
__device__ __align__(16) float g_ctx[HID];                    // context vector
__device__ __align__(16) float g_x[HID];                      // LSTM input
__device__ __align__(16) float g_gates[4 * HID];              // i,f,g,o gates
__device__ __align__(16) float g_h[HID];                      // h_new
__device__ __align__(16) float g_logits[VOC];                 // output logits

// ---------------- helpers ----------------
__device__ __forceinline__ float wred_sum(float v) {
    #pragma unroll
    for (int o = 16; o; o >>= 1) v += __shfl_xor_sync(0xffffffffu, v, o);
    return v;
}
__device__ __forceinline__ float wred_max(float v) {
    #pragma unroll
    for (int o = 16; o; o >>= 1) v = fmaxf(v, __shfl_xor_sync(0xffffffffu, v, o));
    return v;
}
__device__ __forceinline__ float block_sum(float v) {
    __shared__ float sm[33];
    int lane = threadIdx.x & 31, warp = threadIdx.x >> 5;
    v = wred_sum(v);
    if (lane == 0) sm[warp] = v;
    __syncthreads();
    int nw = (blockDim.x + 31) >> 5;
    float r = (threadIdx.x < nw) ? sm[threadIdx.x] : 0.f;
    if (warp == 0) { r = wred_sum(r); if (lane == 0) sm[32] = r; }
    __syncthreads();
    r = sm[32];
    __syncthreads();
    return r;
}
__device__ __forceinline__ float block_max(float v) {
    __shared__ float sm[33];
    int lane = threadIdx.x & 31, warp = threadIdx.x >> 5;
    v = wred_max(v);
    if (lane == 0) sm[warp] = v;
    __syncthreads();
    int nw = (blockDim.x + 31) >> 5;
    float r = (threadIdx.x < nw) ? sm[threadIdx.x] : -INFINITY;
    if (warp == 0) { r = wred_max(r); if (lane == 0) sm[32] = r; }
    __syncthreads();
    r = sm[32];
    __syncthreads();
    return r;
}

__device__ __forceinline__ float dot4(float4 w, float4 x, float acc) {
    return fmaf(w.x, x.x, fmaf(w.y, x.y, fmaf(w.z, x.z, fmaf(w.w, x.w, acc))));
}

// ---------------- kernels ----------------

// out[row] = ACT( W1[row]·v1 + (C2 ? W2[row]·v2 : 0) + b1[row] + (b2 ? b2[row] : 0) )
// warp-per-row. Weights streamed with __ldcs (no reuse), vectors via __ldg (L2-resident).
// If idx1 != nullptr, v1 is a 2D table and the row used is idx1[0] (embedding fusion).
template<int C1, int C2, int ACT>
__global__ void k_gemv2(const float* __restrict__ W1, int ld1,
                        const float* __restrict__ v1, const int* __restrict__ idx1,
                        const float* __restrict__ W2, int ld2, const float* __restrict__ v2,
                        const float* __restrict__ b1, const float* __restrict__ b2,
                        float* __restrict__ out)
{
    const int lane = threadIdx.x & 31;
    const int row  = blockIdx.x * (blockDim.x >> 5) + (threadIdx.x >> 5);

    const float* vv1 = idx1 ? (v1 + (size_t)idx1[0] * C1) : v1;
    const float4* w1 = reinterpret_cast<const float4*>(W1 + (size_t)row * ld1);
    const float4* a1 = reinterpret_cast<const float4*>(vv1);

    float acc0 = 0.f, acc1 = 0.f;
    #pragma unroll 4
    for (int k0 = 0; k0 < C1 / 4; k0 += 64) {
        int k = k0 + lane;
        float4 w = __ldcs(w1 + k);
        float4 x = __ldg(a1 + k);
        acc0 = dot4(w, x, acc0);
        w = __ldcs(w1 + k + 32);
        x = __ldg(a1 + k + 32);
        acc1 = dot4(w, x, acc1);
    }
    if constexpr (C2 > 0) {
        const float4* w2 = reinterpret_cast<const float4*>(W2 + (size_t)row * ld2);
        const float4* a2 = reinterpret_cast<const float4*>(v2);
        #pragma unroll 4
        for (int k0 = 0; k0 < C2 / 4; k0 += 64) {
            int k = k0 + lane;
            float4 w = __ldcs(w2 + k);
            float4 x = __ldg(a2 + k);
            acc0 = dot4(w, x, acc0);
            w = __ldcs(w2 + k + 32);
            x = __ldg(a2 + k + 32);
            acc1 = dot4(w, x, acc1);
        }
    }
    float acc = wred_sum(acc0 + acc1);
    if (lane == 0) {
        acc += b1[row];
        if (b2) acc += b2[row];
        if (ACT == 1) acc = fmaxf(acc, 0.f);
        out[row] = acc;
    }
}

// softmax over 2048 attention logits; writes g_attn and d_out[12288:14336)
__global__ void k_softmax_attn(float* __restrict__ out_attn) {
    const int t = threadIdx.x;           // 256 threads, 8 elems each
    float v[8];
    float m = -INFINITY;
    #pragma unroll
    for (int i = 0; i < 8; i++) {
        v[i] = g_alog[t + 256 * i];
        m = fmaxf(m, v[i]);
    }
    m = block_max(m);
    float s = 0.f;
    #pragma unroll
    for (int i = 0; i < 8; i++) {
        v[i] = expf(v[i] - m);
        s += v[i];
    }
    s = block_sum(s);
    float inv = 1.f / s;
    #pragma unroll
    for (int i = 0; i < 8; i++) {
        float w = v[i] * inv;
        g_attn[t + 256 * i]   = w;
        out_attn[t + 256 * i] = w;
    }
}

// ctx partial: grid(4, 128), block 256. Each block: 1024 cols (256 float4) × 16 rows.
// 512 blocks, 128K threads, 16 fully-unrolled independent loads per thread.
__global__ void k_ctx_partial(const float* __restrict__ enc) {
    const int col4 = blockIdx.x * 256 + threadIdx.x;    // 0..1023
    const int l0   = blockIdx.y * 16;
    const float4* e4 = reinterpret_cast<const float4*>(enc);
    float4 acc = make_float4(0.f, 0.f, 0.f, 0.f);
    #pragma unroll
    for (int i = 0; i < 16; ++i) {
        int l = l0 + i;
        float w = g_attn[l];
        float4 u = __ldcs(e4 + (size_t)l * (HID / 4) + col4);
        acc.x = fmaf(w, u.x, acc.x);
        acc.y = fmaf(w, u.y, acc.y);
        acc.z = fmaf(w, u.z, acc.z);
        acc.w = fmaf(w, u.w, acc.w);
    }
    reinterpret_cast<float4*>(g_ctx_part)[blockIdx.y * (HID / 4) + col4] = acc;
}

// ctx reduce: 32 blocks x 128 threads; 4 warps split the 128 slices,
// fixed-order combine via shared memory (deterministic).
__global__ void k_ctx_reduce() {
    const int col4 = blockIdx.x * 32 + (threadIdx.x & 31); // 0..1023
    const int quad = threadIdx.x >> 5;                     // 0..3
    __shared__ float4 sm[4][32];
    const float4* p = reinterpret_cast<const float4*>(g_ctx_part);
    float4 a = make_float4(0.f, 0.f, 0.f, 0.f);
    #pragma unroll 8
    for (int s = quad * 32; s < quad * 32 + 32; ++s) {
        float4 u = p[(size_t)s * (HID / 4) + col4];
        a.x += u.x; a.y += u.y; a.z += u.z; a.w += u.w;
    }
    sm[quad][threadIdx.x & 31] = a;
    __syncthreads();
    if (quad == 0) {
        float4 r = sm[0][threadIdx.x];
        #pragma unroll
        for (int q = 1; q < 4; q++) {
            float4 u = sm[q][threadIdx.x];
            r.x += u.x; r.y += u.y; r.z += u.z; r.w += u.w;
        }
        reinterpret_cast<float4*>(g_ctx)[col4] = r;
    }
}

// LSTM pointwise -> h_new, c_new; writes d_out[4096:8192)=h_new, d_out[8192:12288)=c_new
__global__ void k_lstm(const float* __restrict__ c_in, float* __restrict__ out) {
    const int j = blockIdx.x * blockDim.x + threadIdx.x;  // 0..4095
    float gi = g_gates[j];
    float gf = g_gates[HID + j];
    float gg = g_gates[2 * HID + j];
    float go = g_gates[3 * HID + j];
    float si = 1.f / (1.f + expf(-gi));
    float sf = 1.f / (1.f + expf(-gf));
    float so = 1.f / (1.f + expf(-go));
    float cn = sf * c_in[j] + si * tanhf(gg);
    float hn = so * tanhf(cn);
    g_h[j] = hn;
    out[HID + j]     = hn;
    out[2 * HID + j] = cn;
}

// log-softmax over 4096 logits -> d_out[0:4096)
__global__ void k_logsoftmax(float* __restrict__ out) {
    const int t = threadIdx.x;           // 1024 threads, 4 elems each
    float v[4];
    float m = -INFINITY;
    #pragma unroll
    for (int i = 0; i < 4; i++) {
        v[i] = g_logits[t + 1024 * i];
        m = fmaxf(m, v[i]);
    }
    m = block_max(m);
    float s = 0.f;
    #pragma unroll
    for (int i = 0; i < 4; i++) s += expf(v[i] - m);
    s = block_sum(s);
    float lse = m + logf(s);
    #pragma unroll
    for (int i = 0; i < 4; i++) out[t + 1024 * i] = v[i] - lse;
}

// ---------------- launch ----------------
extern "C" void kernel_launch(void* const* d_in, const int* in_sizes, int n_in,
                              void* d_out, int out_size)
{
    const int*   token  = (const int*)  d_in[0];
    const float* h      = (const float*)d_in[1];
    const float* c      = (const float*)d_in[2];
    const float* enc    = (const float*)d_in[3];
    const float* emb    = (const float*)d_in[4];
    const float* W_attn = (const float*)d_in[5];
    const float* b_attn = (const float*)d_in[6];
    const float* W_comb = (const float*)d_in[7];
    const float* b_comb = (const float*)d_in[8];
    const float* W_ih   = (const float*)d_in[9];
    const float* W_hh   = (const float*)d_in[10];
    const float* b_ih   = (const float*)d_in[11];
    const float* b_hh   = (const float*)d_in[12];
    const float* W_out  = (const float*)d_in[13];
    const float* b_out  = (const float*)d_in[14];
    float* out = (float*)d_out;

    // resolve scratch symbol addresses once (host-side query, capture-safe)
    static float *p_alog = nullptr, *p_x, *p_gates, *p_logits, *p_ctx, *p_h;
    if (!p_alog) {
        cudaGetSymbolAddress((void**)&p_alog,   g_alog);
        cudaGetSymbolAddress((void**)&p_x,      g_x);
        cudaGetSymbolAddress((void**)&p_gates,  g_gates);
        cudaGetSymbolAddress((void**)&p_logits, g_logits);
        cudaGetSymbolAddress((void**)&p_ctx,    g_ctx);
        cudaGetSymbolAddress((void**)&p_h,      g_h);
    }

    // 1) attention logits: [emb[token]; h] @ W_attn.T + b_attn  (2048 rows x 8192 cols)
    k_gemv2<4096, 4096, 0><<<LEN / 8, 256>>>(
        W_attn,         8192, emb, token,
        W_attn + 4096,  8192, h,
        b_attn, nullptr, p_alog);

    // 2) softmax -> g_attn and d_out[12288:]
    k_softmax_attn<<<1, 256>>>(out + 3 * HID);

    // 3) ctx = attn_w @ encoder_outputs (deterministic two-stage)
    k_ctx_partial<<<dim3(4, CTX_SLICES), 256>>>(enc);
    k_ctx_reduce<<<32, 128>>>();

    // 4) x = relu([emb[token]; ctx] @ W_comb.T + b_comb)  (4096 rows x 8192 cols)
    k_gemv2<4096, 4096, 1><<<HID / 8, 256>>>(
        W_comb,        8192, emb, token,
        W_comb + 4096, 8192, p_ctx,
        b_comb, nullptr, p_x);

    // 5) gates = x @ W_ih.T + b_ih + h @ W_hh.T + b_hh  (16384 rows)
    k_gemv2<4096, 4096, 0><<<(4 * HID) / 8, 256>>>(
        W_ih, 4096, p_x, nullptr,
        W_hh, 4096, h,
        b_ih, b_hh, p_gates);

    // 6) LSTM pointwise -> h_new, c_new (also written to d_out)
    k_lstm<<<HID / 256, 256>>>(c, out);

    // 7) logits = h_new @ W_out.T + b_out  (4096 rows x 4096 cols)
    k_gemv2<4096, 0, 0><<<VOC / 8, 256>>>(
        W_out, 4096, p_h, nullptr,
        nullptr, 0, nullptr,
        b_out, nullptr, p_logits);

    // 8) log-softmax -> d_out[0:4096)
    k_logsoftmax<<<1, 1024>>>(out);
}